// round 1
// baseline (speedup 1.0000x reference)
#include <cuda_runtime.h>
#include <math.h>

#define BB 32
#define SS 4096
#define DD 1024
#define OO 1024
#define WIN 96                 // Gaussian window half-width: exp(-96^2/128)=5e-32, negligible
#define INV2SS (1.0f/128.0f)   // 1/(2*STDDEV^2), STDDEV=8

// Scratch (no allocs allowed anywhere)
__device__ float g_score[BB * SS];      // 512 KB
__device__ float g_max[BB];
__device__ float g_sum[BB];
__device__ float g_weighted[BB * DD];   // 128 KB

// ---------------------------------------------------------------------------
// Kernel 1: score[b,s] = dot(source[b,s,:], target[b,:])
// grid (S/64, B), 256 threads (8 warps x 8 rows each). Coalesced float4 loads.
// This kernel owns the 512 MB traffic floor — must run at HBM roofline.
// ---------------------------------------------------------------------------
__global__ void __launch_bounds__(256) score_kernel(const float* __restrict__ src,
                                                    const float* __restrict__ tgt) {
    __shared__ float4 st[DD / 4];   // target row, 4 KB
    const int b = blockIdx.y;
    const int tid = threadIdx.x;

    st[tid] = reinterpret_cast<const float4*>(tgt + (size_t)b * DD)[tid];
    __syncthreads();

    const int warp = tid >> 5, lane = tid & 31;
    const int row0 = blockIdx.x * 64 + warp * 8;

    #pragma unroll
    for (int i = 0; i < 8; i++) {
        const int row = row0 + i;
        const float4* s4 = reinterpret_cast<const float4*>(
            src + ((size_t)b * SS + row) * DD);
        float4 a = make_float4(0.f, 0.f, 0.f, 0.f);
        #pragma unroll
        for (int k = 0; k < 8; k++) {
            float4 v = s4[lane + 32 * k];    // 8 independent 16B loads -> MLP
            float4 t = st[lane + 32 * k];
            a.x += v.x * t.x; a.y += v.y * t.y;
            a.z += v.z * t.z; a.w += v.w * t.w;
        }
        float r = (a.x + a.y) + (a.z + a.w);
        #pragma unroll
        for (int off = 16; off; off >>= 1)
            r += __shfl_xor_sync(0xffffffffu, r, off);
        if (lane == 0) g_score[b * SS + row] = r;
    }
}

// ---------------------------------------------------------------------------
// Kernel 2: per-batch softmax stats (max, sum of exp). grid B, 512 threads.
// ---------------------------------------------------------------------------
__global__ void __launch_bounds__(512) stats_kernel() {
    const int b = blockIdx.x, tid = threadIdx.x;
    const int warp = tid >> 5, lane = tid & 31;

    float v[8], m = -1e30f;
    #pragma unroll
    for (int i = 0; i < 8; i++) {
        v[i] = g_score[b * SS + tid + i * 512];
        m = fmaxf(m, v[i]);
    }
    __shared__ float redm[16];
    __shared__ float reds[16];
    #pragma unroll
    for (int off = 16; off; off >>= 1)
        m = fmaxf(m, __shfl_xor_sync(0xffffffffu, m, off));
    if (lane == 0) redm[warp] = m;
    __syncthreads();
    if (tid < 32) {
        float mm = (tid < 16) ? redm[tid] : -1e30f;
        #pragma unroll
        for (int off = 8; off; off >>= 1)
            mm = fmaxf(mm, __shfl_xor_sync(0xffffffffu, mm, off));
        if (tid == 0) redm[0] = mm;
    }
    __syncthreads();
    m = redm[0];

    float s = 0.f;
    #pragma unroll
    for (int i = 0; i < 8; i++) s += expf(v[i] - m);
    #pragma unroll
    for (int off = 16; off; off >>= 1)
        s += __shfl_xor_sync(0xffffffffu, s, off);
    if (lane == 0) reds[warp] = s;
    __syncthreads();
    if (tid < 32) {
        float ss2 = (tid < 16) ? reds[tid] : 0.f;
        #pragma unroll
        for (int off = 8; off; off >>= 1)
            ss2 += __shfl_xor_sync(0xffffffffu, ss2, off);
        if (tid == 0) { g_max[b] = m; g_sum[b] = ss2; }
    }
}

// ---------------------------------------------------------------------------
// Kernel 3: weighted[b,d] = sum over the +-WIN window of w[b,s]*source[b,s,d]
// grid (D/256, B), 256 threads, thread-per-d. Only ~25 MB of source touched.
// ---------------------------------------------------------------------------
__global__ void __launch_bounds__(256) weighted_kernel(const float* __restrict__ src,
                                                       const int* __restrict__ pos) {
    __shared__ float wc[2 * WIN + 1];   // 193 coefficients
    const int b = blockIdx.y;
    const int tid = threadIdx.x;
    const int p = pos[b];
    const int s0 = max(0, p - WIN);
    const int s1 = min(SS - 1, p + WIN);
    const int n = s1 - s0 + 1;

    if (tid < n) {
        const int s = s0 + tid;
        const float rel = (float)(s - p);
        wc[tid] = expf(g_score[b * SS + s] - g_max[b]) * (1.0f / g_sum[b])
                * expf(-rel * rel * INV2SS);
    }
    __syncthreads();

    const int d = blockIdx.x * 256 + tid;
    const float* sp = src + ((size_t)b * SS + s0) * DD + d;
    float acc = 0.f;
    for (int i = 0; i < n; i++)
        acc += wc[i] * sp[(size_t)i * DD];   // coalesced 1KB rows
    g_weighted[b * DD + d] = acc;
}

// ---------------------------------------------------------------------------
// Kernel 4: out = tanh(concat(target, weighted) @ W), C=[32,2048], W=[2048,1024]
// grid O/16 = 64 blocks, 256 threads. W read exactly once (8 MB total).
// Thread layout: oc = tid&15 (output col in tile), br = tid>>4 handles b, b+16.
// ---------------------------------------------------------------------------
__global__ void __launch_bounds__(256) out_kernel(const float* __restrict__ tgt,
                                                  const float* __restrict__ Wm,
                                                  float* __restrict__ out) {
    __shared__ float sC[32][65];   // +1 pad: kills 16-way conflict on sC[br][k]
    __shared__ float sW[64][16];
    const int tid = threadIdx.x;
    const int oc = tid & 15, br = tid >> 4;
    const int obase = blockIdx.x * 16;
    float acc0 = 0.f, acc1 = 0.f;

    for (int kt = 0; kt < 2 * DD; kt += 64) {
        #pragma unroll
        for (int j = 0; j < 8; j++) {         // stage C chunk [32][64]
            const int e = tid + 256 * j;
            const int bb = e >> 6, dd = e & 63;
            const int d = kt + dd;
            sC[bb][dd] = (d < DD) ? tgt[bb * DD + d]
                                  : g_weighted[bb * DD + (d - DD)];
        }
        #pragma unroll
        for (int j = 0; j < 4; j++) {         // stage W chunk [64][16]
            const int e = tid + 256 * j;
            const int kk = e >> 4, ooo = e & 15;
            sW[kk][ooo] = Wm[(size_t)(kt + kk) * OO + obase + ooo];
        }
        __syncthreads();
        #pragma unroll
        for (int k = 0; k < 64; k++) {
            const float w = sW[k][oc];
            acc0 += sC[br][k] * w;
            acc1 += sC[br + 16][k] * w;
        }
        __syncthreads();
    }
    out[(size_t)br * OO + obase + oc]        = tanhf(acc0);
    out[(size_t)(br + 16) * OO + obase + oc] = tanhf(acc1);
}

// ---------------------------------------------------------------------------
extern "C" void kernel_launch(void* const* d_in, const int* in_sizes, int n_in,
                              void* d_out, int out_size) {
    const float* src = (const float*)d_in[0];   // [B,S,D]
    const float* tgt = (const float*)d_in[1];   // [B,D]
    const int*   pos = (const int*)d_in[2];     // [B]
    const float* Wm  = (const float*)d_in[3];   // [2D,O]
    float* out = (float*)d_out;                 // [B,O]

    score_kernel<<<dim3(SS / 64, BB), 256>>>(src, tgt);
    stats_kernel<<<BB, 512>>>();
    weighted_kernel<<<dim3(DD / 256, BB), 256>>>(src, pos);
    out_kernel<<<OO / 16, 256>>>(tgt, Wm, out);
}

// round 2
// speedup vs baseline: 1.4529x; 1.4529x over previous
#include <cuda_runtime.h>
#include <math.h>

#define BB 32
#define SS 4096
#define DD 1024
#define OO 1024
#define WIN 96                 // Gaussian window half-width: exp(-96^2/128)=5e-32, negligible
#define INV2SS (1.0f/128.0f)   // 1/(2*STDDEV^2), STDDEV=8
#define KS 16                  // K-splits for epilogue GEMM (2048/128)
#define KT 128                 // K per split
#define OT 64                  // output cols per block

// Scratch (no allocs allowed anywhere)
__device__ float g_score[BB * SS];        // 512 KB
__device__ float g_max[BB];
__device__ float g_sum[BB];
__device__ float g_weighted[BB * DD];     // 128 KB
__device__ float g_part[KS * BB * OO];    // 2 MB split-K partials

// ---------------------------------------------------------------------------
// Kernel 1: score[b,s] = dot(source[b,s,:], target[b,:])
// grid (S/64, B), 256 threads (8 warps x 8 rows each). Owns the 512 MB floor.
// ---------------------------------------------------------------------------
__global__ void __launch_bounds__(256) score_kernel(const float* __restrict__ src,
                                                    const float* __restrict__ tgt) {
    __shared__ float4 st[DD / 4];   // target row, 4 KB
    const int b = blockIdx.y;
    const int tid = threadIdx.x;

    st[tid] = reinterpret_cast<const float4*>(tgt + (size_t)b * DD)[tid];
    __syncthreads();

    const int warp = tid >> 5, lane = tid & 31;
    const int row0 = blockIdx.x * 64 + warp * 8;

    #pragma unroll
    for (int i = 0; i < 8; i++) {
        const int row = row0 + i;
        const float4* s4 = reinterpret_cast<const float4*>(
            src + ((size_t)b * SS + row) * DD);
        float4 a = make_float4(0.f, 0.f, 0.f, 0.f);
        #pragma unroll
        for (int k = 0; k < 8; k++) {
            float4 v = s4[lane + 32 * k];    // 8 independent 16B loads -> MLP
            float4 t = st[lane + 32 * k];
            a.x += v.x * t.x; a.y += v.y * t.y;
            a.z += v.z * t.z; a.w += v.w * t.w;
        }
        float r = (a.x + a.y) + (a.z + a.w);
        #pragma unroll
        for (int off = 16; off; off >>= 1)
            r += __shfl_xor_sync(0xffffffffu, r, off);
        if (lane == 0) g_score[b * SS + row] = r;
    }
}

// ---------------------------------------------------------------------------
// Kernel 2: per-batch softmax stats (max, sum of exp). grid B, 512 threads.
// ---------------------------------------------------------------------------
__global__ void __launch_bounds__(512) stats_kernel() {
    const int b = blockIdx.x, tid = threadIdx.x;
    const int warp = tid >> 5, lane = tid & 31;

    float v[8], m = -1e30f;
    #pragma unroll
    for (int i = 0; i < 8; i++) {
        v[i] = g_score[b * SS + tid + i * 512];
        m = fmaxf(m, v[i]);
    }
    __shared__ float redm[16];
    __shared__ float reds[16];
    #pragma unroll
    for (int off = 16; off; off >>= 1)
        m = fmaxf(m, __shfl_xor_sync(0xffffffffu, m, off));
    if (lane == 0) redm[warp] = m;
    __syncthreads();
    if (tid < 32) {
        float mm = (tid < 16) ? redm[tid] : -1e30f;
        #pragma unroll
        for (int off = 8; off; off >>= 1)
            mm = fmaxf(mm, __shfl_xor_sync(0xffffffffu, mm, off));
        if (tid == 0) redm[0] = mm;
    }
    __syncthreads();
    m = redm[0];

    float s = 0.f;
    #pragma unroll
    for (int i = 0; i < 8; i++) s += expf(v[i] - m);
    #pragma unroll
    for (int off = 16; off; off >>= 1)
        s += __shfl_xor_sync(0xffffffffu, s, off);
    if (lane == 0) reds[warp] = s;
    __syncthreads();
    if (tid < 32) {
        float ss2 = (tid < 16) ? reds[tid] : 0.f;
        #pragma unroll
        for (int off = 8; off; off >>= 1)
            ss2 += __shfl_xor_sync(0xffffffffu, ss2, off);
        if (tid == 0) { g_max[b] = m; g_sum[b] = ss2; }
    }
}

// ---------------------------------------------------------------------------
// Kernel 3: weighted[b,d] = sum over the +-WIN window of w[b,s]*source[b,s,d]
// grid (D/256, B), 256 threads, thread-per-d. Only ~25 MB of source touched.
// ---------------------------------------------------------------------------
__global__ void __launch_bounds__(256) weighted_kernel(const float* __restrict__ src,
                                                       const int* __restrict__ pos) {
    __shared__ float wc[2 * WIN + 1];   // 193 coefficients
    const int b = blockIdx.y;
    const int tid = threadIdx.x;
    const int p = pos[b];
    const int s0 = max(0, p - WIN);
    const int s1 = min(SS - 1, p + WIN);
    const int n = s1 - s0 + 1;

    if (tid < n) {
        const int s = s0 + tid;
        const float rel = (float)(s - p);
        wc[tid] = expf(g_score[b * SS + s] - g_max[b]) * (1.0f / g_sum[b])
                * expf(-rel * rel * INV2SS);
    }
    __syncthreads();

    const int d = blockIdx.x * 256 + tid;
    const float* sp = src + ((size_t)b * SS + s0) * DD + d;
    float acc = 0.f;
    for (int i = 0; i < n; i++)
        acc += wc[i] * sp[(size_t)i * DD];   // coalesced 1KB rows
    g_weighted[b * DD + d] = acc;
}

// ---------------------------------------------------------------------------
// Kernel 4a: split-K partial GEMM. C=[32,2048] (concat), W=[2048,1024].
// grid (O/OT=16, KS=16) = 256 blocks, 256 threads.
// Each block: full 32 batches x 64 output cols over a 128-wide K slice.
// K slices of 128 align with the concat boundary (1024), so each block reads
// purely target (ks<8) or purely weighted (ks>=8) — no per-element select.
// ---------------------------------------------------------------------------
__global__ void __launch_bounds__(256) out_partial(const float* __restrict__ tgt,
                                                   const float* __restrict__ Wm) {
    __shared__ float sC[BB][KT];       // 16 KB
    __shared__ float sW[KT][OT];       // 32 KB
    const int tid = threadIdx.x;
    const int obase = blockIdx.x * OT;
    const int ks = blockIdx.y;
    const int kg0 = ks * KT;
    const float* cbase = (kg0 < DD) ? tgt : g_weighted;
    const int koff = kg0 & (DD - 1);

    // stage C slice [32][128]: 4096 elems, 16 per thread, coalesced
    #pragma unroll
    for (int j = 0; j < 16; j++) {
        const int e = tid + 256 * j;
        sC[e >> 7][e & 127] = cbase[(e >> 7) * DD + koff + (e & 127)];
    }
    // stage W slice [128][64]: 8192 elems, 32 per thread, coalesced
    #pragma unroll
    for (int j = 0; j < 32; j++) {
        const int e = tid + 256 * j;
        sW[e >> 6][e & 63] = Wm[(size_t)(kg0 + (e >> 6)) * OO + obase + (e & 63)];
    }
    __syncthreads();

    const int oc = tid & 63;       // within warp: consecutive -> conflict-free sW
    const int bq = tid >> 6;       // 0..3, each owns 8 batches
    float acc[8];
    #pragma unroll
    for (int i = 0; i < 8; i++) acc[i] = 0.f;

    #pragma unroll 4
    for (int k = 0; k < KT; k++) {
        const float w = sW[k][oc];
        #pragma unroll
        for (int i = 0; i < 8; i++)
            acc[i] += sC[bq * 8 + i][k] * w;   // broadcast reads
    }

    #pragma unroll
    for (int i = 0; i < 8; i++)
        g_part[((size_t)ks * BB + bq * 8 + i) * OO + obase + oc] = acc[i];
}

// ---------------------------------------------------------------------------
// Kernel 4b: out[b,o] = tanh(sum_ks part[ks,b,o]). 32768 threads.
// ---------------------------------------------------------------------------
__global__ void __launch_bounds__(256) out_reduce(float* __restrict__ out) {
    const int idx = blockIdx.x * 256 + threadIdx.x;   // b*OO + o
    float s = 0.f;
    #pragma unroll
    for (int ks = 0; ks < KS; ks++)
        s += g_part[(size_t)ks * BB * OO + idx];
    out[idx] = tanhf(s);
}

// ---------------------------------------------------------------------------
extern "C" void kernel_launch(void* const* d_in, const int* in_sizes, int n_in,
                              void* d_out, int out_size) {
    const float* src = (const float*)d_in[0];   // [B,S,D]
    const float* tgt = (const float*)d_in[1];   // [B,D]
    const int*   pos = (const int*)d_in[2];     // [B]
    const float* Wm  = (const float*)d_in[3];   // [2D,O]
    float* out = (float*)d_out;                 // [B,O]

    score_kernel<<<dim3(SS / 64, BB), 256>>>(src, tgt);
    stats_kernel<<<BB, 512>>>();
    weighted_kernel<<<dim3(DD / 256, BB), 256>>>(src, pos);
    out_partial<<<dim3(OO / OT, KS), 256>>>(tgt, Wm);
    out_reduce<<<BB * OO / 256, 256>>>(out);
}

// round 3
// speedup vs baseline: 1.4569x; 1.0027x over previous
#include <cuda_runtime.h>
#include <math.h>

#define BB 32
#define SS 4096
#define DD 1024
#define OO 1024
#define WIN 96                 // Gaussian window half-width: exp(-96^2/128)=5e-32, negligible
#define INV2SS (1.0f/128.0f)   // 1/(2*STDDEV^2), STDDEV=8
#define KS 32                  // K-splits for epilogue GEMM (2048/64)
#define KT 64                  // K per split
#define OT 64                  // output cols per block

// Scratch (no allocs allowed anywhere)
__device__ float g_score[BB * SS];        // 512 KB
__device__ float g_max[BB];
__device__ float g_sum[BB];
__device__ float g_weighted[BB * DD];     // 128 KB
__device__ float g_part[KS * BB * OO];    // 4 MB split-K partials

// ---------------------------------------------------------------------------
// Kernel 1: score[b,s] = dot(source[b,s,:], target[b,:])
// grid (S/64, B), 256 threads (8 warps x 8 rows each). Owns the 512 MB floor.
// __ldcs: source is streamed exactly once -> evict-first, keep L2 clean.
// ---------------------------------------------------------------------------
__global__ void __launch_bounds__(256) score_kernel(const float* __restrict__ src,
                                                    const float* __restrict__ tgt) {
    __shared__ float4 st[DD / 4];   // target row, 4 KB
    const int b = blockIdx.y;
    const int tid = threadIdx.x;

    st[tid] = reinterpret_cast<const float4*>(tgt + (size_t)b * DD)[tid];
    __syncthreads();

    const int warp = tid >> 5, lane = tid & 31;
    const int row0 = blockIdx.x * 64 + warp * 8;

    #pragma unroll
    for (int i = 0; i < 8; i++) {
        const int row = row0 + i;
        const float4* s4 = reinterpret_cast<const float4*>(
            src + ((size_t)b * SS + row) * DD);
        float4 a = make_float4(0.f, 0.f, 0.f, 0.f);
        #pragma unroll
        for (int k = 0; k < 8; k++) {
            float4 v = __ldcs(s4 + lane + 32 * k);   // 8 independent 16B streaming loads
            float4 t = st[lane + 32 * k];
            a.x += v.x * t.x; a.y += v.y * t.y;
            a.z += v.z * t.z; a.w += v.w * t.w;
        }
        float r = (a.x + a.y) + (a.z + a.w);
        #pragma unroll
        for (int off = 16; off; off >>= 1)
            r += __shfl_xor_sync(0xffffffffu, r, off);
        if (lane == 0) g_score[b * SS + row] = r;
    }
}

// ---------------------------------------------------------------------------
// Kernel 2: per-batch softmax stats (max, sum of exp). grid B, 512 threads.
// ---------------------------------------------------------------------------
__global__ void __launch_bounds__(512) stats_kernel() {
    const int b = blockIdx.x, tid = threadIdx.x;
    const int warp = tid >> 5, lane = tid & 31;

    const float4* row4 = reinterpret_cast<const float4*>(g_score + b * SS);
    float4 v0 = row4[tid], v1 = row4[tid + 512];
    float m = fmaxf(fmaxf(fmaxf(v0.x, v0.y), fmaxf(v0.z, v0.w)),
                    fmaxf(fmaxf(v1.x, v1.y), fmaxf(v1.z, v1.w)));

    __shared__ float redm[16];
    __shared__ float reds[16];
    #pragma unroll
    for (int off = 16; off; off >>= 1)
        m = fmaxf(m, __shfl_xor_sync(0xffffffffu, m, off));
    if (lane == 0) redm[warp] = m;
    __syncthreads();
    if (tid < 32) {
        float mm = (tid < 16) ? redm[tid] : -1e30f;
        #pragma unroll
        for (int off = 8; off; off >>= 1)
            mm = fmaxf(mm, __shfl_xor_sync(0xffffffffu, mm, off));
        if (tid == 0) redm[0] = mm;
    }
    __syncthreads();
    m = redm[0];

    float s = expf(v0.x - m) + expf(v0.y - m) + expf(v0.z - m) + expf(v0.w - m)
            + expf(v1.x - m) + expf(v1.y - m) + expf(v1.z - m) + expf(v1.w - m);
    #pragma unroll
    for (int off = 16; off; off >>= 1)
        s += __shfl_xor_sync(0xffffffffu, s, off);
    if (lane == 0) reds[warp] = s;
    __syncthreads();
    if (tid < 32) {
        float ss2 = (tid < 16) ? reds[tid] : 0.f;
        #pragma unroll
        for (int off = 8; off; off >>= 1)
            ss2 += __shfl_xor_sync(0xffffffffu, ss2, off);
        if (tid == 0) { g_max[b] = m; g_sum[b] = ss2; }
    }
}

// ---------------------------------------------------------------------------
// Kernel 3: weighted[b,d] = sum over the +-WIN window of w[b,s]*source[b,s,d]
// grid (D/256, B), 256 threads, thread-per-d. Only ~25 MB of source touched.
// ---------------------------------------------------------------------------
__global__ void __launch_bounds__(256) weighted_kernel(const float* __restrict__ src,
                                                       const int* __restrict__ pos) {
    __shared__ float wc[2 * WIN + 1];   // 193 coefficients
    const int b = blockIdx.y;
    const int tid = threadIdx.x;
    const int p = pos[b];
    const int s0 = max(0, p - WIN);
    const int s1 = min(SS - 1, p + WIN);
    const int n = s1 - s0 + 1;

    if (tid < n) {
        const int s = s0 + tid;
        const float rel = (float)(s - p);
        wc[tid] = expf(g_score[b * SS + s] - g_max[b]) * (1.0f / g_sum[b])
                * expf(-rel * rel * INV2SS);
    }
    __syncthreads();

    const int d = blockIdx.x * 256 + tid;
    const float* sp = src + ((size_t)b * SS + s0) * DD + d;
    float acc = 0.f;
    for (int i = 0; i < n; i++)
        acc += wc[i] * sp[(size_t)i * DD];   // coalesced 1KB rows
    g_weighted[b * DD + d] = acc;
}

// ---------------------------------------------------------------------------
// Kernel 4a: split-K partial GEMM. C=[32,2048] (concat), W=[2048,1024].
// grid (O/OT=16, KS=32) = 512 blocks, 256 threads, 24 KB smem.
// K slices of 64 align inside each concat half (boundary at 1024), so each
// block reads purely target (ks<16) or purely weighted (ks>=16).
// ---------------------------------------------------------------------------
__global__ void __launch_bounds__(256) out_partial(const float* __restrict__ tgt,
                                                   const float* __restrict__ Wm) {
    __shared__ float sC[BB][KT];       // 8 KB
    __shared__ float sW[KT][OT];       // 16 KB
    const int tid = threadIdx.x;
    const int obase = blockIdx.x * OT;
    const int ks = blockIdx.y;
    const int kg0 = ks * KT;
    const float* cbase = (kg0 < DD) ? tgt : g_weighted;
    const int koff = kg0 & (DD - 1);

    // stage C slice [32][64] via float4: 512 float4, 2 per thread
    float4* sC4 = reinterpret_cast<float4*>(&sC[0][0]);
    #pragma unroll
    for (int j = 0; j < 2; j++) {
        const int e = tid + 256 * j;           // e = row*16 + c4
        sC4[e] = reinterpret_cast<const float4*>(
            cbase + (e >> 4) * DD + koff)[e & 15];
    }
    // stage W slice [64][64] via float4: 1024 float4, 4 per thread
    float4* sW4 = reinterpret_cast<float4*>(&sW[0][0]);
    #pragma unroll
    for (int j = 0; j < 4; j++) {
        const int e = tid + 256 * j;
        sW4[e] = reinterpret_cast<const float4*>(
            Wm + (size_t)(kg0 + (e >> 4)) * OO + obase)[e & 15];
    }
    __syncthreads();

    const int oc = tid & 63;       // consecutive within warp -> conflict-free sW
    const int bq = tid >> 6;       // 0..3, each owns 8 batches
    float acc[8];
    #pragma unroll
    for (int i = 0; i < 8; i++) acc[i] = 0.f;

    #pragma unroll 8
    for (int k = 0; k < KT; k++) {
        const float w = sW[k][oc];
        #pragma unroll
        for (int i = 0; i < 8; i++)
            acc[i] += sC[bq * 8 + i][k] * w;   // broadcast reads
    }

    #pragma unroll
    for (int i = 0; i < 8; i++)
        g_part[((size_t)ks * BB + bq * 8 + i) * OO + obase + oc] = acc[i];
}

// ---------------------------------------------------------------------------
// Kernel 4b: out[b,o] = tanh(sum_ks part[ks,b,o]). float4, 8192 lanes.
// ---------------------------------------------------------------------------
__global__ void __launch_bounds__(256) out_reduce(float* __restrict__ out) {
    const int i4 = blockIdx.x * 256 + threadIdx.x;   // float4 index into [B*O]
    const float4* p4 = reinterpret_cast<const float4*>(g_part);
    float4 s = make_float4(0.f, 0.f, 0.f, 0.f);
    #pragma unroll
    for (int ks = 0; ks < KS; ks++) {
        float4 v = p4[(size_t)ks * (BB * OO / 4) + i4];
        s.x += v.x; s.y += v.y; s.z += v.z; s.w += v.w;
    }
    float4 r = make_float4(tanhf(s.x), tanhf(s.y), tanhf(s.z), tanhf(s.w));
    reinterpret_cast<float4*>(out)[i4] = r;
}

// ---------------------------------------------------------------------------
extern "C" void kernel_launch(void* const* d_in, const int* in_sizes, int n_in,
                              void* d_out, int out_size) {
    const float* src = (const float*)d_in[0];   // [B,S,D]
    const float* tgt = (const float*)d_in[1];   // [B,D]
    const int*   pos = (const int*)d_in[2];     // [B]
    const float* Wm  = (const float*)d_in[3];   // [2D,O]
    float* out = (float*)d_out;                 // [B,O]

    score_kernel<<<dim3(SS / 64, BB), 256>>>(src, tgt);
    stats_kernel<<<BB, 512>>>();
    weighted_kernel<<<dim3(DD / 256, BB), 256>>>(src, pos);
    out_partial<<<dim3(OO / OT, KS), 256>>>(tgt, Wm);
    out_reduce<<<BB * OO / 4 / 256, 256>>>(out);
}